// round 3
// baseline (speedup 1.0000x reference)
#include <cuda_runtime.h>
#include <math.h>

#define BATCH 2
#define SEQ 2048
#define DM 1024
#define NH 16
#define DH 64
#define MTOT (BATCH * SEQ)   // 4096

// Scratch (allocation-free rule: __device__ globals)
__device__ float g_q[BATCH * NH * SEQ * DH];     // [bh][s][d]
__device__ float g_k[BATCH * NH * SEQ * DH];
__device__ float g_v[BATCH * NH * SEQ * DH];
__device__ float g_attn[BATCH * SEQ * DM];       // [b][s][h*64+d]

// ---------------------------------------------------------------------------
// NT GEMM: C[m,n] = sum_k A[m,k] * W[n,k]   (M=4096, N=K=1024)
// mode 0: plain row-major write to Cout (output projection, A = g_attn)
// mode 1: headed layout + RoPE (Q / K), dst selected by `which`
// mode 2: headed layout, no RoPE (V)
// Tiles: BM=BN=128, BK=16, 256 threads, 8x8 per thread.
// ---------------------------------------------------------------------------
__global__ __launch_bounds__(256) void gemm_nt_kernel(
    const float* __restrict__ A, const float* __restrict__ W,
    const int* __restrict__ pos, float* __restrict__ Cout,
    int mode, int which)
{
    __shared__ float As[16][132];   // [k][m], padded
    __shared__ float Bs[16][132];   // [k][n], padded

    const int tid = threadIdx.x;
    const int tx = tid & 15;
    const int ty = tid >> 4;
    const int bx = blockIdx.x;      // N tile (8)
    const int by = blockIdx.y;      // M tile (32)

    const float* Ain = (mode == 0) ? g_attn : A;
    const int aRow = by * 128;
    const int bRow = bx * 128;

    float acc[8][8];
#pragma unroll
    for (int i = 0; i < 8; i++)
#pragma unroll
        for (int j = 0; j < 8; j++) acc[i][j] = 0.0f;

    for (int k0 = 0; k0 < DM; k0 += 16) {
#pragma unroll
        for (int j = 0; j < 2; j++) {
            int f = tid + j * 256;          // 512 float4 per operand tile
            int mr = f >> 2;                // 0..127
            int kq = (f & 3) << 2;          // 0,4,8,12
            float4 av = *(const float4*)&Ain[(size_t)(aRow + mr) * DM + k0 + kq];
            As[kq + 0][mr] = av.x; As[kq + 1][mr] = av.y;
            As[kq + 2][mr] = av.z; As[kq + 3][mr] = av.w;
            float4 wv = *(const float4*)&W[(size_t)(bRow + mr) * DM + k0 + kq];
            Bs[kq + 0][mr] = wv.x; Bs[kq + 1][mr] = wv.y;
            Bs[kq + 2][mr] = wv.z; Bs[kq + 3][mr] = wv.w;
        }
        __syncthreads();

#pragma unroll
        for (int kk = 0; kk < 16; kk++) {
            float4 a0 = *(const float4*)&As[kk][ty * 8];
            float4 a1 = *(const float4*)&As[kk][ty * 8 + 4];
            float4 b0 = *(const float4*)&Bs[kk][tx * 8];
            float4 b1 = *(const float4*)&Bs[kk][tx * 8 + 4];
            float a[8] = {a0.x, a0.y, a0.z, a0.w, a1.x, a1.y, a1.z, a1.w};
            float b[8] = {b0.x, b0.y, b0.z, b0.w, b1.x, b1.y, b1.z, b1.w};
#pragma unroll
            for (int i = 0; i < 8; i++)
#pragma unroll
                for (int j = 0; j < 8; j++)
                    acc[i][j] += a[i] * b[j];
        }
        __syncthreads();
    }

    const int m0 = aRow + ty * 8;
    const int n0 = bRow + tx * 8;

    if (mode == 0) {
#pragma unroll
        for (int i = 0; i < 8; i++) {
            float4 c0 = make_float4(acc[i][0], acc[i][1], acc[i][2], acc[i][3]);
            float4 c1 = make_float4(acc[i][4], acc[i][5], acc[i][6], acc[i][7]);
            *(float4*)&Cout[(size_t)(m0 + i) * DM + n0]     = c0;
            *(float4*)&Cout[(size_t)(m0 + i) * DM + n0 + 4] = c1;
        }
        return;
    }

    float* dst = (which == 0) ? g_q : (which == 1) ? g_k : g_v;
    const int h = n0 >> 6;          // 8 cols never cross a head boundary
    const int dbase = n0 & 63;

    if (mode == 2) {
#pragma unroll
        for (int i = 0; i < 8; i++) {
            int m = m0 + i;
            int b = m >> 11;            // / SEQ
            int s = m & (SEQ - 1);
            size_t idx = (((size_t)(b * NH + h)) * SEQ + s) * DH + dbase;
            *(float4*)&dst[idx]     = make_float4(acc[i][0], acc[i][1], acc[i][2], acc[i][3]);
            *(float4*)&dst[idx + 4] = make_float4(acc[i][4], acc[i][5], acc[i][6], acc[i][7]);
        }
        return;
    }

    // mode 1: RoPE. Columns come in (even, odd) interleaved pairs.
    float invf[4];
#pragma unroll
    for (int jp = 0; jp < 4; jp++) {
        int dd = dbase + 2 * jp;    // even index within head
        invf[jp] = (float)exp((double)dd * -0.14391156831212787);  // ln(1e4)/64
    }
#pragma unroll
    for (int i = 0; i < 8; i++) {
        int m = m0 + i;
        int b = m >> 11;
        int s = m & (SEQ - 1);
        float p = (float)pos[s];
        size_t idx = (((size_t)(b * NH + h)) * SEQ + s) * DH + dbase;
#pragma unroll
        for (int jp = 0; jp < 4; jp++) {
            float ang = p * invf[jp];
            float sn, cs;
            sincosf(ang, &sn, &cs);
            float e = acc[i][2 * jp];
            float o = acc[i][2 * jp + 1];
            dst[idx + 2 * jp]     = e * cs - o * sn;
            dst[idx + 2 * jp + 1] = e * sn + o * cs;
        }
    }
}

// ---------------------------------------------------------------------------
// Flash attention, fp32, causal. Per block: one (bh, 64-query tile).
// 256 threads, 4x4 microtiles over 64x64 score / output tiles.
// smem: Qs,Ks as [d][q] (pitch 68), Vs,Ps natural [k][d]/[q][k] (pitch 68).
// ---------------------------------------------------------------------------
#define FPITCH 68
#define FLASH_SMEM (4 * 64 * FPITCH * 4)   // 69632 bytes

__global__ __launch_bounds__(256) void flash_kernel()
{
    extern __shared__ float sm[];
    float* Qs = sm;
    float* Ks = sm + 64 * FPITCH;
    float* Vs = sm + 2 * 64 * FPITCH;
    float* Ps = sm + 3 * 64 * FPITCH;

    const int qt = blockIdx.x;
    const int bh = blockIdx.y;
    const int tid = threadIdx.x;
    const int tx = tid & 15;
    const int ty = tid >> 4;
    const int qbase = qt * 64;

    const float* Qg = g_q + (size_t)bh * SEQ * DH;
    const float* Kg = g_k + (size_t)bh * SEQ * DH;
    const float* Vg = g_v + (size_t)bh * SEQ * DH;

    // Load Q tile transposed: Qs[d][q]
#pragma unroll
    for (int j = 0; j < 4; j++) {
        int f = tid + j * 256;          // 1024 float4
        int r = f >> 4;                 // q row 0..63
        int d4 = (f & 15) << 2;
        float4 qv = *(const float4*)&Qg[(size_t)(qbase + r) * DH + d4];
        Qs[(d4 + 0) * FPITCH + r] = qv.x;
        Qs[(d4 + 1) * FPITCH + r] = qv.y;
        Qs[(d4 + 2) * FPITCH + r] = qv.z;
        Qs[(d4 + 3) * FPITCH + r] = qv.w;
    }

    float o[4][4];
    float mrun[4], lrun[4];
#pragma unroll
    for (int r = 0; r < 4; r++) {
        mrun[r] = -1e30f;
        lrun[r] = 0.0f;
#pragma unroll
        for (int c = 0; c < 4; c++) o[r][c] = 0.0f;
    }

    for (int kt = 0; kt <= qt; kt++) {
        const int kbase = kt * 64;
        // Load K transposed, V natural
#pragma unroll
        for (int j = 0; j < 4; j++) {
            int f = tid + j * 256;
            int r = f >> 4;
            int d4 = (f & 15) << 2;
            float4 kv = *(const float4*)&Kg[(size_t)(kbase + r) * DH + d4];
            Ks[(d4 + 0) * FPITCH + r] = kv.x;
            Ks[(d4 + 1) * FPITCH + r] = kv.y;
            Ks[(d4 + 2) * FPITCH + r] = kv.z;
            Ks[(d4 + 3) * FPITCH + r] = kv.w;
            float4 vv = *(const float4*)&Vg[(size_t)(kbase + r) * DH + d4];
            *(float4*)&Vs[r * FPITCH + d4] = vv;
        }
        __syncthreads();

        // S = Q K^T for this tile (4x4 per thread)
        float s[4][4];
#pragma unroll
        for (int r = 0; r < 4; r++)
#pragma unroll
            for (int c = 0; c < 4; c++) s[r][c] = 0.0f;

#pragma unroll
        for (int kk = 0; kk < 64; kk++) {
            float4 q4 = *(const float4*)&Qs[kk * FPITCH + ty * 4];
            float4 k4 = *(const float4*)&Ks[kk * FPITCH + tx * 4];
            float qa[4] = {q4.x, q4.y, q4.z, q4.w};
            float ka[4] = {k4.x, k4.y, k4.z, k4.w};
#pragma unroll
            for (int r = 0; r < 4; r++)
#pragma unroll
                for (int c = 0; c < 4; c++)
                    s[r][c] += qa[r] * ka[c];
        }

        // Online softmax update, per row
#pragma unroll
        for (int r = 0; r < 4; r++) {
            int qa_idx = qbase + ty * 4 + r;
            float mx = -1e30f;
#pragma unroll
            for (int c = 0; c < 4; c++) {
                int ka_idx = kbase + tx * 4 + c;
                float sv = s[r][c] * 0.125f;
                if (ka_idx > qa_idx) sv = -1e30f;
                s[r][c] = sv;
                mx = fmaxf(mx, sv);
            }
#pragma unroll
            for (int msk = 1; msk < 16; msk <<= 1)
                mx = fmaxf(mx, __shfl_xor_sync(0xffffffffu, mx, msk));
            float mnew = fmaxf(mrun[r], mx);
            float fac = expf(mrun[r] - mnew);
            mrun[r] = mnew;
            float rs = 0.0f;
#pragma unroll
            for (int c = 0; c < 4; c++) {
                float pv = expf(s[r][c] - mnew);
                s[r][c] = pv;
                rs += pv;
            }
#pragma unroll
            for (int msk = 1; msk < 16; msk <<= 1)
                rs += __shfl_xor_sync(0xffffffffu, rs, msk);
            lrun[r] = lrun[r] * fac + rs;
#pragma unroll
            for (int c = 0; c < 4; c++) o[r][c] *= fac;
            *(float4*)&Ps[(ty * 4 + r) * FPITCH + tx * 4] =
                make_float4(s[r][0], s[r][1], s[r][2], s[r][3]);
        }
        __syncthreads();

        // O += P V  (4x4 per thread)
#pragma unroll
        for (int kk = 0; kk < 64; kk++) {
            float4 v4 = *(const float4*)&Vs[kk * FPITCH + tx * 4];
#pragma unroll
            for (int r = 0; r < 4; r++) {
                float pr = Ps[(ty * 4 + r) * FPITCH + kk];
                o[r][0] += pr * v4.x;
                o[r][1] += pr * v4.y;
                o[r][2] += pr * v4.z;
                o[r][3] += pr * v4.w;
            }
        }
        __syncthreads();
    }

    // Write normalized output to g_attn in [b][s][h*64+d] layout
    const int b = bh >> 4;
    const int h = bh & 15;
#pragma unroll
    for (int r = 0; r < 4; r++) {
        float inv = 1.0f / lrun[r];
        int sa = qbase + ty * 4 + r;
        size_t idx = ((size_t)b * SEQ + sa) * DM + h * 64 + tx * 4;
        *(float4*)&g_attn[idx] =
            make_float4(o[r][0] * inv, o[r][1] * inv, o[r][2] * inv, o[r][3] * inv);
    }
}

// ---------------------------------------------------------------------------
extern "C" void kernel_launch(void* const* d_in, const int* in_sizes, int n_in,
                              void* d_out, int out_size)
{
    const float* x  = (const float*)d_in[0];
    const int* pos  = (const int*)d_in[1];
    const float* wq = (const float*)d_in[2];
    const float* wk = (const float*)d_in[3];
    const float* wv = (const float*)d_in[4];
    const float* wo = (const float*)d_in[5];
    float* out = (float*)d_out;

    dim3 gemm_grid(DM / 128, MTOT / 128);   // (8, 32)

    gemm_nt_kernel<<<gemm_grid, 256>>>(x, wq, pos, nullptr, 1, 0);  // Q + RoPE
    gemm_nt_kernel<<<gemm_grid, 256>>>(x, wk, pos, nullptr, 1, 1);  // K + RoPE
    gemm_nt_kernel<<<gemm_grid, 256>>>(x, wv, pos, nullptr, 2, 2);  // V

    cudaFuncSetAttribute(flash_kernel,
                         cudaFuncAttributeMaxDynamicSharedMemorySize, FLASH_SMEM);
    flash_kernel<<<dim3(SEQ / 64, BATCH * NH), 256, FLASH_SMEM>>>();

    gemm_nt_kernel<<<gemm_grid, 256>>>(nullptr, wo, pos, out, 0, 3); // O proj
}

// round 4
// speedup vs baseline: 1.0093x; 1.0093x over previous
#include <cuda_runtime.h>
#include <math.h>

#define BATCH 2
#define SEQ 2048
#define DM 1024
#define NH 16
#define DH 64
#define MTOT (BATCH * SEQ)   // 4096

// Scratch (allocation-free rule: __device__ globals)
__device__ float g_q[BATCH * NH * SEQ * DH];     // [bh][s][d]
__device__ float g_k[BATCH * NH * SEQ * DH];
__device__ float g_v[BATCH * NH * SEQ * DH];
__device__ float g_attn[BATCH * SEQ * DM];       // [b][s][h*64+d]

// ---------------------------------------------------------------------------
// NT GEMM: C[m,n] = sum_k A[m,k] * W[n,k]   (M=4096, N=K=1024)
// mode 0: plain row-major write to Cout (output projection, A = g_attn)
// mode 1: headed layout + RoPE (Q / K), dst selected by `which`
// mode 2: headed layout, no RoPE (V)
// Tiles: BM=BN=128, BK=16, 256 threads, 8x8 per thread.
// ---------------------------------------------------------------------------
__global__ __launch_bounds__(256) void gemm_nt_kernel(
    const float* __restrict__ A, const float* __restrict__ W,
    const int* __restrict__ pos, float* __restrict__ Cout,
    int mode, int which)
{
    __shared__ float As[16][132];   // [k][m], padded
    __shared__ float Bs[16][132];   // [k][n], padded

    const int tid = threadIdx.x;
    const int tx = tid & 15;
    const int ty = tid >> 4;
    const int bx = blockIdx.x;      // N tile (8)
    const int by = blockIdx.y;      // M tile (32)

    const float* Ain = (mode == 0) ? g_attn : A;
    const int aRow = by * 128;
    const int bRow = bx * 128;

    float acc[8][8];
#pragma unroll
    for (int i = 0; i < 8; i++)
#pragma unroll
        for (int j = 0; j < 8; j++) acc[i][j] = 0.0f;

    for (int k0 = 0; k0 < DM; k0 += 16) {
#pragma unroll
        for (int j = 0; j < 2; j++) {
            int f = tid + j * 256;          // 512 float4 per operand tile
            int mr = f >> 2;                // 0..127
            int kq = (f & 3) << 2;          // 0,4,8,12
            float4 av = *(const float4*)&Ain[(size_t)(aRow + mr) * DM + k0 + kq];
            As[kq + 0][mr] = av.x; As[kq + 1][mr] = av.y;
            As[kq + 2][mr] = av.z; As[kq + 3][mr] = av.w;
            float4 wv = *(const float4*)&W[(size_t)(bRow + mr) * DM + k0 + kq];
            Bs[kq + 0][mr] = wv.x; Bs[kq + 1][mr] = wv.y;
            Bs[kq + 2][mr] = wv.z; Bs[kq + 3][mr] = wv.w;
        }
        __syncthreads();

#pragma unroll
        for (int kk = 0; kk < 16; kk++) {
            float4 a0 = *(const float4*)&As[kk][ty * 8];
            float4 a1 = *(const float4*)&As[kk][ty * 8 + 4];
            float4 b0 = *(const float4*)&Bs[kk][tx * 8];
            float4 b1 = *(const float4*)&Bs[kk][tx * 8 + 4];
            float a[8] = {a0.x, a0.y, a0.z, a0.w, a1.x, a1.y, a1.z, a1.w};
            float b[8] = {b0.x, b0.y, b0.z, b0.w, b1.x, b1.y, b1.z, b1.w};
#pragma unroll
            for (int i = 0; i < 8; i++)
#pragma unroll
                for (int j = 0; j < 8; j++)
                    acc[i][j] += a[i] * b[j];
        }
        __syncthreads();
    }

    const int m0 = aRow + ty * 8;
    const int n0 = bRow + tx * 8;

    if (mode == 0) {
#pragma unroll
        for (int i = 0; i < 8; i++) {
            float4 c0 = make_float4(acc[i][0], acc[i][1], acc[i][2], acc[i][3]);
            float4 c1 = make_float4(acc[i][4], acc[i][5], acc[i][6], acc[i][7]);
            *(float4*)&Cout[(size_t)(m0 + i) * DM + n0]     = c0;
            *(float4*)&Cout[(size_t)(m0 + i) * DM + n0 + 4] = c1;
        }
        return;
    }

    float* dst = (which == 0) ? g_q : (which == 1) ? g_k : g_v;
    const int h = n0 >> 6;          // 8 cols never cross a head boundary
    const int dbase = n0 & 63;

    if (mode == 2) {
#pragma unroll
        for (int i = 0; i < 8; i++) {
            int m = m0 + i;
            int b = m >> 11;            // / SEQ
            int s = m & (SEQ - 1);
            size_t idx = (((size_t)(b * NH + h)) * SEQ + s) * DH + dbase;
            *(float4*)&dst[idx]     = make_float4(acc[i][0], acc[i][1], acc[i][2], acc[i][3]);
            *(float4*)&dst[idx + 4] = make_float4(acc[i][4], acc[i][5], acc[i][6], acc[i][7]);
        }
        return;
    }

    // mode 1: RoPE. Columns come in (even, odd) interleaved pairs.
    float invf[4];
#pragma unroll
    for (int jp = 0; jp < 4; jp++) {
        int dd = dbase + 2 * jp;    // even index within head
        invf[jp] = (float)exp((double)dd * -0.14391156831212787);  // ln(1e4)/64
    }
#pragma unroll
    for (int i = 0; i < 8; i++) {
        int m = m0 + i;
        int b = m >> 11;
        int s = m & (SEQ - 1);
        float p = (float)pos[s];
        size_t idx = (((size_t)(b * NH + h)) * SEQ + s) * DH + dbase;
#pragma unroll
        for (int jp = 0; jp < 4; jp++) {
            float ang = p * invf[jp];
            float sn, cs;
            sincosf(ang, &sn, &cs);
            float e = acc[i][2 * jp];
            float o = acc[i][2 * jp + 1];
            dst[idx + 2 * jp]     = e * cs - o * sn;
            dst[idx + 2 * jp + 1] = e * sn + o * cs;
        }
    }
}

// ---------------------------------------------------------------------------
// Flash attention, fp32, causal. Per block: one (bh, 64-query tile).
// 256 threads, 4x4 microtiles over 64x64 score / output tiles.
// smem: Qs,Ks as [d][q] (pitch 68), Vs,Ps natural [k][d]/[q][k] (pitch 68).
// ---------------------------------------------------------------------------
#define FPITCH 68
#define FLASH_SMEM (4 * 64 * FPITCH * 4)   // 69632 bytes

__global__ __launch_bounds__(256) void flash_kernel()
{
    extern __shared__ float sm[];
    float* Qs = sm;
    float* Ks = sm + 64 * FPITCH;
    float* Vs = sm + 2 * 64 * FPITCH;
    float* Ps = sm + 3 * 64 * FPITCH;

    const int qt = blockIdx.x;
    const int bh = blockIdx.y;
    const int tid = threadIdx.x;
    const int tx = tid & 15;
    const int ty = tid >> 4;
    const int qbase = qt * 64;

    const float* Qg = g_q + (size_t)bh * SEQ * DH;
    const float* Kg = g_k + (size_t)bh * SEQ * DH;
    const float* Vg = g_v + (size_t)bh * SEQ * DH;

    // Load Q tile transposed: Qs[d][q]
#pragma unroll
    for (int j = 0; j < 4; j++) {
        int f = tid + j * 256;          // 1024 float4
        int r = f >> 4;                 // q row 0..63
        int d4 = (f & 15) << 2;
        float4 qv = *(const float4*)&Qg[(size_t)(qbase + r) * DH + d4];
        Qs[(d4 + 0) * FPITCH + r] = qv.x;
        Qs[(d4 + 1) * FPITCH + r] = qv.y;
        Qs[(d4 + 2) * FPITCH + r] = qv.z;
        Qs[(d4 + 3) * FPITCH + r] = qv.w;
    }

    float o[4][4];
    float mrun[4], lrun[4];
#pragma unroll
    for (int r = 0; r < 4; r++) {
        mrun[r] = -1e30f;
        lrun[r] = 0.0f;
#pragma unroll
        for (int c = 0; c < 4; c++) o[r][c] = 0.0f;
    }

    for (int kt = 0; kt <= qt; kt++) {
        const int kbase = kt * 64;
        // Load K transposed, V natural
#pragma unroll
        for (int j = 0; j < 4; j++) {
            int f = tid + j * 256;
            int r = f >> 4;
            int d4 = (f & 15) << 2;
            float4 kv = *(const float4*)&Kg[(size_t)(kbase + r) * DH + d4];
            Ks[(d4 + 0) * FPITCH + r] = kv.x;
            Ks[(d4 + 1) * FPITCH + r] = kv.y;
            Ks[(d4 + 2) * FPITCH + r] = kv.z;
            Ks[(d4 + 3) * FPITCH + r] = kv.w;
            float4 vv = *(const float4*)&Vg[(size_t)(kbase + r) * DH + d4];
            *(float4*)&Vs[r * FPITCH + d4] = vv;
        }
        __syncthreads();

        // S = Q K^T for this tile (4x4 per thread)
        float s[4][4];
#pragma unroll
        for (int r = 0; r < 4; r++)
#pragma unroll
            for (int c = 0; c < 4; c++) s[r][c] = 0.0f;

#pragma unroll
        for (int kk = 0; kk < 64; kk++) {
            float4 q4 = *(const float4*)&Qs[kk * FPITCH + ty * 4];
            float4 k4 = *(const float4*)&Ks[kk * FPITCH + tx * 4];
            float qa[4] = {q4.x, q4.y, q4.z, q4.w};
            float ka[4] = {k4.x, k4.y, k4.z, k4.w};
#pragma unroll
            for (int r = 0; r < 4; r++)
#pragma unroll
                for (int c = 0; c < 4; c++)
                    s[r][c] += qa[r] * ka[c];
        }

        // Online softmax update, per row
#pragma unroll
        for (int r = 0; r < 4; r++) {
            int qa_idx = qbase + ty * 4 + r;
            float mx = -1e30f;
#pragma unroll
            for (int c = 0; c < 4; c++) {
                int ka_idx = kbase + tx * 4 + c;
                float sv = s[r][c] * 0.125f;
                if (ka_idx > qa_idx) sv = -1e30f;
                s[r][c] = sv;
                mx = fmaxf(mx, sv);
            }
#pragma unroll
            for (int msk = 1; msk < 16; msk <<= 1)
                mx = fmaxf(mx, __shfl_xor_sync(0xffffffffu, mx, msk));
            float mnew = fmaxf(mrun[r], mx);
            float fac = expf(mrun[r] - mnew);
            mrun[r] = mnew;
            float rs = 0.0f;
#pragma unroll
            for (int c = 0; c < 4; c++) {
                float pv = expf(s[r][c] - mnew);
                s[r][c] = pv;
                rs += pv;
            }
#pragma unroll
            for (int msk = 1; msk < 16; msk <<= 1)
                rs += __shfl_xor_sync(0xffffffffu, rs, msk);
            lrun[r] = lrun[r] * fac + rs;
#pragma unroll
            for (int c = 0; c < 4; c++) o[r][c] *= fac;
            *(float4*)&Ps[(ty * 4 + r) * FPITCH + tx * 4] =
                make_float4(s[r][0], s[r][1], s[r][2], s[r][3]);
        }
        __syncthreads();

        // O += P V  (4x4 per thread)
#pragma unroll
        for (int kk = 0; kk < 64; kk++) {
            float4 v4 = *(const float4*)&Vs[kk * FPITCH + tx * 4];
#pragma unroll
            for (int r = 0; r < 4; r++) {
                float pr = Ps[(ty * 4 + r) * FPITCH + kk];
                o[r][0] += pr * v4.x;
                o[r][1] += pr * v4.y;
                o[r][2] += pr * v4.z;
                o[r][3] += pr * v4.w;
            }
        }
        __syncthreads();
    }

    // Write normalized output to g_attn in [b][s][h*64+d] layout
    const int b = bh >> 4;
    const int h = bh & 15;
#pragma unroll
    for (int r = 0; r < 4; r++) {
        float inv = 1.0f / lrun[r];
        int sa = qbase + ty * 4 + r;
        size_t idx = ((size_t)b * SEQ + sa) * DM + h * 64 + tx * 4;
        *(float4*)&g_attn[idx] =
            make_float4(o[r][0] * inv, o[r][1] * inv, o[r][2] * inv, o[r][3] * inv);
    }
}

// ---------------------------------------------------------------------------
extern "C" void kernel_launch(void* const* d_in, const int* in_sizes, int n_in,
                              void* d_out, int out_size)
{
    const float* x  = (const float*)d_in[0];
    const int* pos  = (const int*)d_in[1];
    const float* wq = (const float*)d_in[2];
    const float* wk = (const float*)d_in[3];
    const float* wv = (const float*)d_in[4];
    const float* wo = (const float*)d_in[5];
    float* out = (float*)d_out;

    dim3 gemm_grid(DM / 128, MTOT / 128);   // (8, 32)

    gemm_nt_kernel<<<gemm_grid, 256>>>(x, wq, pos, nullptr, 1, 0);  // Q + RoPE
    gemm_nt_kernel<<<gemm_grid, 256>>>(x, wk, pos, nullptr, 1, 1);  // K + RoPE
    gemm_nt_kernel<<<gemm_grid, 256>>>(x, wv, pos, nullptr, 2, 2);  // V

    cudaFuncSetAttribute(flash_kernel,
                         cudaFuncAttributeMaxDynamicSharedMemorySize, FLASH_SMEM);
    flash_kernel<<<dim3(SEQ / 64, BATCH * NH), 256, FLASH_SMEM>>>();

    gemm_nt_kernel<<<gemm_grid, 256>>>(nullptr, wo, pos, out, 0, 3); // O proj
}